// round 8
// baseline (speedup 1.0000x reference)
#include <cuda_runtime.h>
#include <cstdint>
#include <math.h>

// Problem constants (fixed shapes)
#define NTOK 8192          // B*T
#define HDIM 1024
#define IDIM 2048
#define NEXP 8
#define NSLOT (NTOK*2)     // top_k = 2

// GEMM tiling
#define BM 128
#define BN 128
#define BK 16
#define STAGES 3
#define PADK 20            // BK + 4 padding (conflict-free scalar LDS)

// ---------------- scratch (device globals: no allocations allowed) ----------
__device__ int   g_counts[NEXP];
__device__ int   g_cursors[NEXP];
__device__ int   g_offsets[NEXP+1];
__device__ int   g_topk_idx[NTOK*2];
__device__ float g_topk_val[NTOK*2];
__device__ int   g_slot_tok[NSLOT];      // slot -> token
__device__ int   g_tok_slot[NTOK*2];     // (token,k) -> slot
__device__ float g_hid[(size_t)NSLOT * IDIM];    // 128 MB fc1 activations
__device__ float g_out2[(size_t)NSLOT * HDIM];   //  64 MB fc2 per-slot outputs

// ---------------- helpers ----------------------------------------------------
__device__ __forceinline__ uint32_t f2tf(float x){
  uint32_t u; asm("cvt.rna.tf32.f32 %0, %1;" : "=r"(u) : "f"(x));
  return u;
}
__device__ __forceinline__ float silu_f(float v){
  return v * (1.0f / (1.0f + __expf(-v)));
}
__device__ __forceinline__ void cpasync16(void* s, const void* g){
  uint32_t sa = (uint32_t)__cvta_generic_to_shared(s);
  asm volatile("cp.async.cg.shared.global [%0], [%1], 16;" :: "r"(sa), "l"(g));
}
__device__ __forceinline__ void mma_tf32(float* c, const uint32_t* a, const uint32_t* b){
  asm volatile(
    "mma.sync.aligned.m16n8k8.row.col.f32.tf32.tf32.f32 "
    "{%0,%1,%2,%3}, {%4,%5,%6,%7}, {%8,%9}, {%0,%1,%2,%3};\n"
    : "+f"(c[0]), "+f"(c[1]), "+f"(c[2]), "+f"(c[3])
    : "r"(a[0]), "r"(a[1]), "r"(a[2]), "r"(a[3]),
      "r"(b[0]), "r"(b[1]));
}

// ---------------- routing kernels --------------------------------------------
__global__ void k_init(){
  if (threadIdx.x < NEXP) g_counts[threadIdx.x] = 0;
}

// One warp per token: logits = x . Wg^T (fp32 exact), softmax, top-2.
__global__ void k_gate(const float* __restrict__ x, const float* __restrict__ Wg){
  int gid  = blockIdx.x * blockDim.x + threadIdx.x;
  int n    = gid >> 5;
  int lane = gid & 31;
  if (n >= NTOK) return;
  const float* xr = x + (size_t)n * HDIM;
  float acc[NEXP];
  #pragma unroll
  for (int e = 0; e < NEXP; ++e) acc[e] = 0.f;
  for (int h = lane; h < HDIM; h += 32){
    float xv = xr[h];
    #pragma unroll
    for (int e = 0; e < NEXP; ++e) acc[e] = fmaf(xv, Wg[e*HDIM + h], acc[e]);
  }
  #pragma unroll
  for (int e = 0; e < NEXP; ++e){
    #pragma unroll
    for (int o = 16; o > 0; o >>= 1) acc[e] += __shfl_xor_sync(0xffffffffu, acc[e], o);
  }
  float mx = acc[0];
  #pragma unroll
  for (int e = 1; e < NEXP; ++e) mx = fmaxf(mx, acc[e]);
  float p[NEXP], s = 0.f;
  #pragma unroll
  for (int e = 0; e < NEXP; ++e){ p[e] = __expf(acc[e] - mx); s += p[e]; }
  float inv = 1.f / s;
  // top-2, strict > keeps lowest index on ties (matches jax.lax.top_k)
  int i0 = 0; float v0 = p[0];
  #pragma unroll
  for (int e = 1; e < NEXP; ++e) if (p[e] > v0){ v0 = p[e]; i0 = e; }
  int i1 = -1; float v1 = -1.f;
  #pragma unroll
  for (int e = 0; e < NEXP; ++e) if (e != i0 && p[e] > v1){ v1 = p[e]; i1 = e; }
  if (lane == 0){
    g_topk_idx[2*n]   = i0; g_topk_val[2*n]   = v0 * inv;
    g_topk_idx[2*n+1] = i1; g_topk_val[2*n+1] = v1 * inv;
    atomicAdd(&g_counts[i0], 1);
    atomicAdd(&g_counts[i1], 1);
  }
}

__global__ void k_offsets(){
  if (threadIdx.x == 0){
    int s = 0;
    for (int e = 0; e < NEXP; ++e){ g_offsets[e] = s; g_cursors[e] = s; s += g_counts[e]; }
    g_offsets[NEXP] = s;
  }
}

__global__ void k_scatter(){
  int n = blockIdx.x * blockDim.x + threadIdx.x;
  if (n >= NTOK) return;
  #pragma unroll
  for (int k = 0; k < 2; ++k){
    int e   = g_topk_idx[2*n + k];
    int pos = atomicAdd(&g_cursors[e], 1);
    g_slot_tok[pos]    = n;
    g_tok_slot[2*n+k]  = pos;
  }
}

// ---------------- grouped GEMM ------------------------------------------------
// MODE 0 (fc1): g_hid[slot, i] = silu( sum_h x[tok[slot],h] * W1[e,i,h] )
//   A: gathered x rows (K = HDIM), B: W1[e] (k-contig rows), N = IDIM
// MODE 1 (fc2): g_out2[slot, h] = sum_i g_hid[slot,i] * W2[e,h,i]   (no weights here)
//   A: g_hid rows (K = IDIM), B: W2[e] (k-contig rows), N = HDIM
// BM=BN=128, BK=16, 256 threads (8 warps 4x2, warp tile 32x64),
// 3-stage cp.async pipeline, mma.sync m16n8k8 tf32, cvt.rna at frag load.
template<int MODE>
__global__ __launch_bounds__(256, 2) void k_gemm(const float* __restrict__ Asrc,
                                                 const float* __restrict__ Wsrc){
  constexpr int KD = (MODE == 0) ? HDIM : IDIM;
  constexpr int KT = KD / BK;

  const int e   = blockIdx.z;
  const int off = g_offsets[e];
  const int Me  = g_offsets[e+1] - off;
  const int m0  = blockIdx.y * BM;
  if (m0 >= Me) return;
  const int n0  = blockIdx.x * BN;
  const float* Bbase = Wsrc + (size_t)e * (size_t)HDIM * (size_t)IDIM;
  float* Outb = (MODE == 0) ? g_hid : g_out2;
  constexpr int ODIM = (MODE == 0) ? IDIM : HDIM;

  // dynamic smem carve: [Arow ptrs 1024][rowSlot 512][As][Bs]
  extern __shared__ char smraw[];
  const float** Arow = (const float**)smraw;
  int*   rowSlot = (int*)(smraw + 1024);
  float* Asb = (float*)(smraw + 1536);
  float* Bsb = Asb + STAGES * BM * PADK;

  const int tid = threadIdx.x;
  if (tid < BM){
    int gr = m0 + tid;
    if (gr < Me){
      int slot = off + gr;
      Arow[tid]    = (MODE == 0) ? (Asrc + (size_t)g_slot_tok[slot] * HDIM)
                                 : (g_hid + (size_t)slot * IDIM);
      rowSlot[tid] = slot;
    } else {
      Arow[tid]    = (MODE == 0) ? Asrc : g_hid;  // safe dummy row
      rowSlot[tid] = -1;
    }
  }
  __syncthreads();

  // per-thread cp.async sources/dests: 2 A rows + 2 B rows, one float4 each
  const int lr  = tid >> 2;          // 0..63
  const int lc  = (tid & 3) * 4;     // 0,4,8,12
  const float* apt0 = Arow[lr]      + lc;
  const float* apt1 = Arow[lr + 64] + lc;
  const float* bpt0 = Bbase + (size_t)(n0 + lr)      * KD + lc;
  const float* bpt1 = Bbase + (size_t)(n0 + lr + 64) * KD + lc;

  auto issue = [&](int kt){
    float* As = Asb + (kt % STAGES) * BM * PADK;
    float* Bs = Bsb + (kt % STAGES) * BN * PADK;
    const int ko = kt * BK;
    cpasync16(As + lr*PADK + lc,        apt0 + ko);
    cpasync16(As + (lr+64)*PADK + lc,   apt1 + ko);
    cpasync16(Bs + lr*PADK + lc,        bpt0 + ko);
    cpasync16(Bs + (lr+64)*PADK + lc,   bpt1 + ko);
  };

  issue(0); asm volatile("cp.async.commit_group;" ::: "memory");
  issue(1); asm volatile("cp.async.commit_group;" ::: "memory");

  const int lane = tid & 31, warp = tid >> 5;
  const int wm = warp >> 1, wn = warp & 1;   // 4 x 2 warps -> 32 x 64 warp tile
  const int g = lane >> 2, tig = lane & 3;

  float c[2][8][4];
  #pragma unroll
  for (int mi = 0; mi < 2; ++mi)
    #pragma unroll
    for (int ni = 0; ni < 8; ++ni)
      #pragma unroll
      for (int j = 0; j < 4; ++j) c[mi][ni][j] = 0.f;

  for (int kt = 0; kt < KT; ++kt){
    asm volatile("cp.async.wait_group 1;" ::: "memory");
    __syncthreads();
    if (kt + 2 < KT) issue(kt + 2);
    asm volatile("cp.async.commit_group;" ::: "memory");

    const float* As = Asb + (kt % STAGES) * BM * PADK;
    const float* Bs = Bsb + (kt % STAGES) * BN * PADK;

    #pragma unroll
    for (int ks = 0; ks < 2; ++ks){
      const int k0 = ks * 8;
      uint32_t a[2][4], b[8][2];
      #pragma unroll
      for (int mi = 0; mi < 2; ++mi){
        const int r = wm*32 + mi*16 + g;
        a[mi][0] = f2tf(As[(r    )*PADK + k0 + tig]);
        a[mi][1] = f2tf(As[(r + 8)*PADK + k0 + tig]);
        a[mi][2] = f2tf(As[(r    )*PADK + k0 + tig + 4]);
        a[mi][3] = f2tf(As[(r + 8)*PADK + k0 + tig + 4]);
      }
      #pragma unroll
      for (int ni = 0; ni < 8; ++ni){
        const int bn = wn*64 + ni*8 + g;
        b[ni][0] = f2tf(Bs[bn*PADK + k0 + tig]);
        b[ni][1] = f2tf(Bs[bn*PADK + k0 + tig + 4]);
      }
      #pragma unroll
      for (int mi = 0; mi < 2; ++mi)
        #pragma unroll
        for (int ni = 0; ni < 8; ++ni)
          mma_tf32(c[mi][ni], a[mi], b[ni]);
    }
  }

  // epilogue: rows indexed by slot in BOTH modes
  #pragma unroll
  for (int mi = 0; mi < 2; ++mi){
    const int r0 = wm*32 + mi*16 + g;
    const int r1 = r0 + 8;
    const int s0 = rowSlot[r0];
    const int s1 = rowSlot[r1];
    #pragma unroll
    for (int ni = 0; ni < 8; ++ni){
      const int col = n0 + wn*64 + ni*8 + 2*tig;
      if (MODE == 0){
        if (s0 >= 0){
          float2 v = make_float2(silu_f(c[mi][ni][0]), silu_f(c[mi][ni][1]));
          *(float2*)(Outb + (size_t)s0 * ODIM + col) = v;
        }
        if (s1 >= 0){
          float2 v = make_float2(silu_f(c[mi][ni][2]), silu_f(c[mi][ni][3]));
          *(float2*)(Outb + (size_t)s1 * ODIM + col) = v;
        }
      } else {
        if (s0 >= 0){
          float2 v = make_float2(c[mi][ni][0], c[mi][ni][1]);
          *(float2*)(Outb + (size_t)s0 * ODIM + col) = v;
        }
        if (s1 >= 0){
          float2 v = make_float2(c[mi][ni][2], c[mi][ni][3]);
          *(float2*)(Outb + (size_t)s1 * ODIM + col) = v;
        }
      }
    }
  }
}

// ---------------- combine: out[n] = w0*out2[s0] + w1*out2[s1] -----------------
__global__ void k_combine(float* __restrict__ out){
  const int idx = blockIdx.x * blockDim.x + threadIdx.x;   // NTOK * 256 threads
  const int n = idx >> 8;                 // 256 float4 per row (HDIM/4)
  const int c = (idx & 255) * 4;
  const int s0 = g_tok_slot[2*n], s1 = g_tok_slot[2*n+1];
  const float w0 = g_topk_val[2*n], w1 = g_topk_val[2*n+1];
  const float4 v0 = *(const float4*)(g_out2 + (size_t)s0 * HDIM + c);
  const float4 v1 = *(const float4*)(g_out2 + (size_t)s1 * HDIM + c);
  float4 r;
  r.x = fmaf(w0, v0.x, w1 * v1.x);
  r.y = fmaf(w0, v0.y, w1 * v1.y);
  r.z = fmaf(w0, v0.z, w1 * v1.z);
  r.w = fmaf(w0, v0.w, w1 * v1.w);
  *(float4*)(out + (size_t)n * HDIM + c) = r;
}

// ---------------- launch ------------------------------------------------------
extern "C" void kernel_launch(void* const* d_in, const int* in_sizes, int n_in,
                              void* d_out, int out_size){
  const float* x  = (const float*)d_in[0];   // [4,2048,1024]
  const float* Wg = (const float*)d_in[1];   // [8,1024]
  const float* W1 = (const float*)d_in[2];   // [8,2048,1024]
  const float* W2 = (const float*)d_in[3];   // [8,1024,2048]
  float* out = (float*)d_out;                // [4,2048,1024]
  (void)in_sizes; (void)n_in; (void)out_size; // top_k hardcoded = 2

  const int smem_bytes = 1536 + STAGES * (BM + BN) * PADK * (int)sizeof(float); // 62976
  cudaFuncSetAttribute(k_gemm<0>, cudaFuncAttributeMaxDynamicSharedMemorySize, smem_bytes);
  cudaFuncSetAttribute(k_gemm<1>, cudaFuncAttributeMaxDynamicSharedMemorySize, smem_bytes);

  k_init<<<1, 32>>>();
  k_gate<<<NTOK/8, 256>>>(x, Wg);
  k_offsets<<<1, 32>>>();
  k_scatter<<<NTOK/256, 256>>>();
  // fc1: N = IDIM (2048) -> 16 n-tiles; up to 128 m-tiles per expert (early exit)
  k_gemm<0><<<dim3(IDIM/BN, NSLOT/BM, NEXP), 256, smem_bytes>>>(x, W1);
  // fc2: N = HDIM (1024) -> 8 n-tiles
  k_gemm<1><<<dim3(HDIM/BN, NSLOT/BM, NEXP), 256, smem_bytes>>>(nullptr, W2);
  k_combine<<<NTOK, 256>>>(out);
}

// round 13
// speedup vs baseline: 1.5090x; 1.5090x over previous
#include <cuda_runtime.h>
#include <cstdint>
#include <math.h>

// Problem constants (fixed shapes)
#define NTOK 8192          // B*T
#define HDIM 1024
#define IDIM 2048
#define NEXP 8
#define NSLOT (NTOK*2)     // top_k = 2
#define NPAD  (NSLOT + 1152)  // padded slot capacity (expert regions 128-aligned)

// GEMM tiling
#define BM 128
#define BN 128
#define BK 16
#define STAGES 5
#define ROWF 20                   // padded row stride in floats (80 B, conflict-free)
#define STAGE_F (128 * ROWF)      // floats per operand per stage
#define SMEM_FLOATS (2 * STAGES * STAGE_F)   // 25600 floats = 102400 B

// ---------------- scratch (device globals: no allocations allowed) ----------
__device__ int   g_counts[NEXP];
__device__ int   g_offsets[NEXP+1];          // 128-aligned expert region starts
__device__ int   g_topk_idx[NTOK*2];
__device__ float g_topk_val[NTOK*2];
__device__ int   g_tok_slot[NTOK*2];         // (token,k) -> padded slot
__device__ float g_xg  [(size_t)NPAD * HDIM];   // gathered + tf32-rounded x
__device__ float g_hid [(size_t)NPAD * IDIM];   // fc1 activations (tf32-rounded)
__device__ float g_out2[(size_t)NPAD * HDIM];   // fc2 per-slot outputs
__device__ float g_W1t[(size_t)NEXP * IDIM * HDIM];  // tf32-rounded W1
__device__ float g_W2t[(size_t)NEXP * HDIM * IDIM];  // tf32-rounded W2

// ---------------- helpers ----------------------------------------------------
__device__ __forceinline__ float rnaf(float x){
  uint32_t u; asm("cvt.rna.tf32.f32 %0, %1;" : "=r"(u) : "f"(x));
  return __uint_as_float(u);
}
__device__ __forceinline__ float silu_f(float v){
  return v * (1.0f / (1.0f + __expf(-v)));
}
__device__ __forceinline__ void cpasync16(uint32_t saddr, const void* g){
  asm volatile("cp.async.cg.shared.global [%0], [%1], 16;" :: "r"(saddr), "l"(g));
}
__device__ __forceinline__ void mma_tf32(float* c, const uint32_t* a, const uint32_t* b){
  asm volatile(
    "mma.sync.aligned.m16n8k8.row.col.f32.tf32.tf32.f32 "
    "{%0,%1,%2,%3}, {%4,%5,%6,%7}, {%8,%9}, {%0,%1,%2,%3};\n"
    : "+f"(c[0]), "+f"(c[1]), "+f"(c[2]), "+f"(c[3])
    : "r"(a[0]), "r"(a[1]), "r"(a[2]), "r"(a[3]),
      "r"(b[0]), "r"(b[1]));
}

// ---------------- routing -----------------------------------------------------
__global__ void k_init(){
  if (threadIdx.x < NEXP) g_counts[threadIdx.x] = 0;
}

// One warp per token: logits (fp32 exact), softmax, top-2.
__global__ void k_gate(const float* __restrict__ x, const float* __restrict__ Wg){
  int gid  = blockIdx.x * blockDim.x + threadIdx.x;
  int n    = gid >> 5;
  int lane = gid & 31;
  if (n >= NTOK) return;
  const float* xr = x + (size_t)n * HDIM;
  float acc[NEXP];
  #pragma unroll
  for (int e = 0; e < NEXP; ++e) acc[e] = 0.f;
  for (int h = lane; h < HDIM; h += 32){
    float xv = xr[h];
    #pragma unroll
    for (int e = 0; e < NEXP; ++e) acc[e] = fmaf(xv, Wg[e*HDIM + h], acc[e]);
  }
  #pragma unroll
  for (int e = 0; e < NEXP; ++e){
    #pragma unroll
    for (int o = 16; o > 0; o >>= 1) acc[e] += __shfl_xor_sync(0xffffffffu, acc[e], o);
  }
  float mx = acc[0];
  #pragma unroll
  for (int e = 1; e < NEXP; ++e) mx = fmaxf(mx, acc[e]);
  float p[NEXP], s = 0.f;
  #pragma unroll
  for (int e = 0; e < NEXP; ++e){ p[e] = __expf(acc[e] - mx); s += p[e]; }
  float inv = 1.f / s;
  // top-2, strict > keeps lowest index on ties (matches jax.lax.top_k)
  int i0 = 0; float v0 = p[0];
  #pragma unroll
  for (int e = 1; e < NEXP; ++e) if (p[e] > v0){ v0 = p[e]; i0 = e; }
  int i1 = -1; float v1 = -1.f;
  #pragma unroll
  for (int e = 0; e < NEXP; ++e) if (e != i0 && p[e] > v1){ v1 = p[e]; i1 = e; }
  if (lane == 0){
    g_topk_idx[2*n]   = i0; g_topk_val[2*n]   = v0 * inv;
    g_topk_idx[2*n+1] = i1; g_topk_val[2*n+1] = v1 * inv;
    atomicAdd(&g_counts[i0], 1);
    atomicAdd(&g_counts[i1], 1);
  }
}

// Fused: 128-aligned offsets + slot assignment. Single block.
__global__ void k_routes(){
  __shared__ int sc[NEXP];
  const int tid = threadIdx.x;
  if (tid == 0){
    int s = 0;
    for (int e = 0; e < NEXP; ++e){
      g_offsets[e] = s;
      s += (g_counts[e] + 127) & ~127;     // pad region to 128 rows
    }
    g_offsets[NEXP] = s;
  }
  __syncthreads();
  if (tid < NEXP) sc[tid] = g_offsets[tid];
  __syncthreads();
  for (int n = tid; n < NTOK; n += blockDim.x){
    #pragma unroll
    for (int k = 0; k < 2; ++k){
      int e = g_topk_idx[2*n + k];
      int pos = atomicAdd(&sc[e], 1);
      g_tok_slot[2*n + k] = pos;
    }
  }
}

// gather x into padded slot order, rounded to tf32 (RNA)
__global__ void k_gatherx(const float* __restrict__ x){
  const int nk   = blockIdx.x;            // 0 .. 2*NTOK-1
  const int slot = g_tok_slot[nk];
  const int tok  = nk >> 1;
  float4 v = ((const float4*)(x + (size_t)tok * HDIM))[threadIdx.x];
  v.x = rnaf(v.x); v.y = rnaf(v.y); v.z = rnaf(v.z); v.w = rnaf(v.w);
  ((float4*)(g_xg + (size_t)slot * HDIM))[threadIdx.x] = v;
}

// round one weight tensor to tf32 (RNA) — 4M float4
__global__ void k_cvtW(const float* __restrict__ src, float* __restrict__ dst){
  int i = blockIdx.x * blockDim.x + threadIdx.x;
  float4 v = ((const float4*)src)[i];
  v.x = rnaf(v.x); v.y = rnaf(v.y); v.z = rnaf(v.z); v.w = rnaf(v.w);
  ((float4*)dst)[i] = v;
}

// ---------------- grouped GEMM (tf32 mma.sync, CVT-free mainloop) -------------
// MODE 0 (fc1): g_hid[slot,i] = rna(silu( sum_h g_xg[slot,h]*W1t[e,i,h] )), K=1024
// MODE 1 (fc2): g_out2[slot,h] =            sum_i g_hid[slot,i]*W2t[e,h,i], K=2048
// BM=BN=128, BK=16, 256 threads (8 warps 4x2, warp 32x64), 5-stage cp.async.
// Expert regions are 128-aligned: no masks anywhere (overrun rows hit zero pad).
template<int MODE>
__global__ __launch_bounds__(256) void k_gemm(){
  constexpr int KD   = (MODE == 0) ? HDIM : IDIM;
  constexpr int KT   = KD / BK;
  constexpr int ODIM = (MODE == 0) ? IDIM : HDIM;

  const int e  = blockIdx.z;
  const int Me = g_counts[e];
  const int m0 = blockIdx.y * BM;
  if (m0 >= Me) return;
  const int rowbase = g_offsets[e] + m0;
  const int n0 = blockIdx.x * BN;

  const float* Abase = ((MODE == 0) ? g_xg : g_hid) + (size_t)rowbase * KD;
  const float* Bbase = ((MODE == 0) ? g_W1t : g_W2t)
                     + (size_t)e * (size_t)HDIM * IDIM + (size_t)n0 * KD;
  float* Outb = (MODE == 0) ? g_hid : g_out2;

  extern __shared__ float sm[];                 // [A stages][B stages]
  float* smA = sm;
  float* smB = sm + STAGES * STAGE_F;

  const int tid = threadIdx.x;

  // per-thread cp.async mapping: 2 A-chunks + 2 B-chunks (16B) per ktile
  const float* ag[2]; const float* bg[2];
  uint32_t asw[2], bsw[2];
  #pragma unroll
  for (int j = 0; j < 2; ++j){
    int i   = tid + 256 * j;       // 0..511 chunk id
    int row = i >> 2;              // 0..127
    int kc  = i & 3;               // 16B chunk within the 64B k-row
    ag[j] = Abase + (size_t)row * KD + kc * 4;
    bg[j] = Bbase + (size_t)row * KD + kc * 4;
    asw[j] = (uint32_t)__cvta_generic_to_shared(smA + row * ROWF + kc * 4);
    bsw[j] = (uint32_t)__cvta_generic_to_shared(smB + row * ROWF + kc * 4);
  }

  auto issue = [&](int kt){
    const uint32_t so = (uint32_t)((kt % STAGES) * STAGE_F * 4);
    const int ko = kt * BK;
    #pragma unroll
    for (int j = 0; j < 2; ++j){
      cpasync16(asw[j] + so, ag[j] + ko);
      cpasync16(bsw[j] + so, bg[j] + ko);
    }
    asm volatile("cp.async.commit_group;" ::: "memory");
  };

  issue(0); issue(1); issue(2); issue(3);

  const int lane = tid & 31, warp = tid >> 5;
  const int wm = warp >> 1, wn = warp & 1;       // 4x2 warps, 32x64 warp tile
  const int g = lane >> 2, tig = lane & 3;

  float c[2][8][4];
  #pragma unroll
  for (int mi = 0; mi < 2; ++mi)
    #pragma unroll
    for (int ni = 0; ni < 8; ++ni)
      #pragma unroll
      for (int j = 0; j < 4; ++j) c[mi][ni][j] = 0.f;

  for (int kt = 0; kt < KT; ++kt){
    asm volatile("cp.async.wait_group 3;" ::: "memory");  // stage kt landed
    __syncthreads();                                      // all warps done with kt-1
    if (kt + 4 < KT) issue(kt + 4);

    const float* As = smA + (kt % STAGES) * STAGE_F;
    const float* Bs = smB + (kt % STAGES) * STAGE_F;

    #pragma unroll
    for (int ks = 0; ks < 2; ++ks){
      const int k0 = ks * 8;
      uint32_t a[2][4], b[8][2];
      #pragma unroll
      for (int mi = 0; mi < 2; ++mi){
        const int r = wm*32 + mi*16 + g;
        a[mi][0] = __float_as_uint(As[(r    )*ROWF + k0 + tig]);
        a[mi][1] = __float_as_uint(As[(r + 8)*ROWF + k0 + tig]);
        a[mi][2] = __float_as_uint(As[(r    )*ROWF + k0 + tig + 4]);
        a[mi][3] = __float_as_uint(As[(r + 8)*ROWF + k0 + tig + 4]);
      }
      #pragma unroll
      for (int ni = 0; ni < 8; ++ni){
        const int bn = wn*64 + ni*8 + g;
        b[ni][0] = __float_as_uint(Bs[bn*ROWF + k0 + tig]);
        b[ni][1] = __float_as_uint(Bs[bn*ROWF + k0 + tig + 4]);
      }
      #pragma unroll
      for (int mi = 0; mi < 2; ++mi)
        #pragma unroll
        for (int ni = 0; ni < 8; ++ni)
          mma_tf32(c[mi][ni], a[mi], b[ni]);
    }
  }

  // epilogue: no masks (pad rows are writable scratch)
  #pragma unroll
  for (int mi = 0; mi < 2; ++mi){
    const int r0 = wm*32 + mi*16 + g;
    float* o0 = Outb + (size_t)(rowbase + r0    ) * ODIM + n0;
    float* o1 = Outb + (size_t)(rowbase + r0 + 8) * ODIM + n0;
    #pragma unroll
    for (int ni = 0; ni < 8; ++ni){
      const int col = wn*64 + ni*8 + 2*tig;
      if (MODE == 0){
        *(float2*)(o0 + col) = make_float2(rnaf(silu_f(c[mi][ni][0])),
                                           rnaf(silu_f(c[mi][ni][1])));
        *(float2*)(o1 + col) = make_float2(rnaf(silu_f(c[mi][ni][2])),
                                           rnaf(silu_f(c[mi][ni][3])));
      } else {
        *(float2*)(o0 + col) = make_float2(c[mi][ni][0], c[mi][ni][1]);
        *(float2*)(o1 + col) = make_float2(c[mi][ni][2], c[mi][ni][3]);
      }
    }
  }
}

// ---------------- combine: out[n] = w0*out2[s0] + w1*out2[s1] -----------------
__global__ void k_combine(float* __restrict__ out){
  const int idx = blockIdx.x * blockDim.x + threadIdx.x;
  const int n = idx >> 8;
  const int c = (idx & 255) * 4;
  const int s0 = g_tok_slot[2*n], s1 = g_tok_slot[2*n+1];
  const float w0 = g_topk_val[2*n], w1 = g_topk_val[2*n+1];
  const float4 v0 = *(const float4*)(g_out2 + (size_t)s0 * HDIM + c);
  const float4 v1 = *(const float4*)(g_out2 + (size_t)s1 * HDIM + c);
  float4 r;
  r.x = fmaf(w0, v0.x, w1 * v1.x);
  r.y = fmaf(w0, v0.y, w1 * v1.y);
  r.z = fmaf(w0, v0.z, w1 * v1.z);
  r.w = fmaf(w0, v0.w, w1 * v1.w);
  *(float4*)(out + (size_t)n * HDIM + c) = r;
}

// ---------------- launch ------------------------------------------------------
// Launch order is chosen so ncu's "-s 5 -c 1" window captures the fc1 GEMM.
extern "C" void kernel_launch(void* const* d_in, const int* in_sizes, int n_in,
                              void* d_out, int out_size){
  const float* x  = (const float*)d_in[0];   // [4,2048,1024]
  const float* Wg = (const float*)d_in[1];   // [8,1024]
  const float* W1 = (const float*)d_in[2];   // [8,2048,1024]
  const float* W2 = (const float*)d_in[3];   // [8,1024,2048]
  float* out = (float*)d_out;                // [4,2048,1024]
  (void)in_sizes; (void)n_in; (void)out_size;

  const int smem_bytes = SMEM_FLOATS * (int)sizeof(float);   // 102400
  cudaFuncSetAttribute(k_gemm<0>, cudaFuncAttributeMaxDynamicSharedMemorySize, smem_bytes);
  cudaFuncSetAttribute(k_gemm<1>, cudaFuncAttributeMaxDynamicSharedMemorySize, smem_bytes);

  float* w1t; float* w2t;
  cudaGetSymbolAddress((void**)&w1t, g_W1t);
  cudaGetSymbolAddress((void**)&w2t, g_W2t);

  k_init   <<<1, 32>>>();                       // 0
  k_gate   <<<NTOK/8, 256>>>(x, Wg);            // 1
  k_routes <<<1, 256>>>();                      // 2
  k_gatherx<<<2*NTOK, 256>>>(x);                // 3
  k_cvtW   <<<16384, 256>>>(W1, w1t);           // 4
  k_gemm<0><<<dim3(IDIM/BN, NSLOT/BM, NEXP), 256, smem_bytes>>>();  // 5  <- profiled
  k_cvtW   <<<16384, 256>>>(W2, w2t);           // 6
  k_gemm<1><<<dim3(HDIM/BN, NSLOT/BM, NEXP), 256, smem_bytes>>>();  // 7
  k_combine<<<NTOK, 256>>>(out);                // 8
}

// round 14
// speedup vs baseline: 1.7035x; 1.1289x over previous
#include <cuda_runtime.h>
#include <cstdint>
#include <math.h>

// Problem constants (fixed shapes)
#define NTOK 8192          // B*T
#define HDIM 1024
#define IDIM 2048
#define NEXP 8
#define NSLOT (NTOK*2)     // top_k = 2
#define NPAD  (NSLOT + 1152)  // padded slot capacity (expert regions 128-aligned)

// GEMM tiling
#define BM 128
#define BN 128
#define BK 32                      // 128-byte k-rows (SW128 chunk swizzle)
#define STAGES 3
#define STAGE_F (128 * BK)         // floats per operand per stage (16 KB)
#define SMEM_FLOATS (2 * STAGES * STAGE_F)   // 24576 floats = 98304 B

// ---------------- scratch (device globals: no allocations allowed) ----------
// NOTE: g_xg / g_hid / W1t / W2t use a PERMUTED k-layout: within each 8-block,
// element order is [k0, k0+4, k0+1, k0+5, k0+2, k0+6, k0+3, k0+7], so an mma
// fragment pair (tig, tig+4) is one contiguous float2.
__device__ int   g_counts[NEXP];
__device__ int   g_offsets[NEXP+1];          // 128-aligned expert region starts
__device__ int   g_topk_idx[NTOK*2];
__device__ float g_topk_val[NTOK*2];
__device__ int   g_tok_slot[NTOK*2];         // (token,k) -> padded slot
__device__ float g_xg  [(size_t)NPAD * HDIM];   // gathered x (tf32, permuted k)
__device__ float g_hid [(size_t)NPAD * IDIM];   // fc1 acts   (tf32, permuted k)
__device__ float g_out2[(size_t)NPAD * HDIM];   // fc2 per-slot outputs (linear)
__device__ float g_W1t[(size_t)NEXP * IDIM * HDIM];  // W1 (tf32, permuted k)
__device__ float g_W2t[(size_t)NEXP * HDIM * IDIM];  // W2 (tf32, permuted k)

// ---------------- helpers ----------------------------------------------------
__device__ __forceinline__ float rnaf(float x){
  uint32_t u; asm("cvt.rna.tf32.f32 %0, %1;" : "=r"(u) : "f"(x));
  return __uint_as_float(u);
}
__device__ __forceinline__ float silu_f(float v){
  return v * (1.0f / (1.0f + __expf(-v)));
}
__device__ __forceinline__ void cpasync16(uint32_t saddr, const void* g){
  asm volatile("cp.async.cg.shared.global [%0], [%1], 16;" :: "r"(saddr), "l"(g));
}
__device__ __forceinline__ void mma_tf32(float* c, const uint32_t* a, const uint32_t* b){
  asm volatile(
    "mma.sync.aligned.m16n8k8.row.col.f32.tf32.tf32.f32 "
    "{%0,%1,%2,%3}, {%4,%5,%6,%7}, {%8,%9}, {%0,%1,%2,%3};\n"
    : "+f"(c[0]), "+f"(c[1]), "+f"(c[2]), "+f"(c[3])
    : "r"(a[0]), "r"(a[1]), "r"(a[2]), "r"(a[3]),
      "r"(b[0]), "r"(b[1]));
}

// ---------------- routing -----------------------------------------------------
// One warp per token: logits (fp32 exact), softmax, top-2.
__global__ void k_gate(const float* __restrict__ x, const float* __restrict__ Wg){
  int gid  = blockIdx.x * blockDim.x + threadIdx.x;
  int n    = gid >> 5;
  int lane = gid & 31;
  if (n >= NTOK) return;
  const float* xr = x + (size_t)n * HDIM;
  float acc[NEXP];
  #pragma unroll
  for (int e = 0; e < NEXP; ++e) acc[e] = 0.f;
  for (int h = lane; h < HDIM; h += 32){
    float xv = xr[h];
    #pragma unroll
    for (int e = 0; e < NEXP; ++e) acc[e] = fmaf(xv, Wg[e*HDIM + h], acc[e]);
  }
  #pragma unroll
  for (int e = 0; e < NEXP; ++e){
    #pragma unroll
    for (int o = 16; o > 0; o >>= 1) acc[e] += __shfl_xor_sync(0xffffffffu, acc[e], o);
  }
  float mx = acc[0];
  #pragma unroll
  for (int e = 1; e < NEXP; ++e) mx = fmaxf(mx, acc[e]);
  float p[NEXP], s = 0.f;
  #pragma unroll
  for (int e = 0; e < NEXP; ++e){ p[e] = __expf(acc[e] - mx); s += p[e]; }
  float inv = 1.f / s;
  // top-2, strict > keeps lowest index on ties (matches jax.lax.top_k)
  int i0 = 0; float v0 = p[0];
  #pragma unroll
  for (int e = 1; e < NEXP; ++e) if (p[e] > v0){ v0 = p[e]; i0 = e; }
  int i1 = -1; float v1 = -1.f;
  #pragma unroll
  for (int e = 0; e < NEXP; ++e) if (e != i0 && p[e] > v1){ v1 = p[e]; i1 = e; }
  if (lane == 0){
    g_topk_idx[2*n]   = i0; g_topk_val[2*n]   = v0 * inv;
    g_topk_idx[2*n+1] = i1; g_topk_val[2*n+1] = v1 * inv;
    atomicAdd(&g_counts[i0], 1);
    atomicAdd(&g_counts[i1], 1);
  }
}

// Fused: 128-aligned offsets + slot assignment. Single block.
__global__ void k_routes(){
  __shared__ int sc[NEXP];
  const int tid = threadIdx.x;
  if (tid == 0){
    int s = 0;
    for (int e = 0; e < NEXP; ++e){
      g_offsets[e] = s;
      s += (g_counts[e] + 127) & ~127;     // pad region to 128 rows
    }
    g_offsets[NEXP] = s;
  }
  __syncthreads();
  if (tid < NEXP) sc[tid] = g_offsets[tid];
  __syncthreads();
  for (int n = tid; n < NTOK; n += blockDim.x){
    #pragma unroll
    for (int k = 0; k < 2; ++k){
      int e = g_topk_idx[2*n + k];
      int pos = atomicAdd(&sc[e], 1);
      g_tok_slot[2*n + k] = pos;
    }
  }
}

// Fused prep: tf32-round + k-permute W1, W2, and the gathered x rows.
// Each thread handles one logical 8-block: load lo4/hi4, write interleaved.
//   blocks [0, 8192)      : W1  (16.7M floats / 8 / 256)
//   blocks [8192, 16384)  : W2
//   blocks [16384, 24576) : gather x into slot order
__global__ void k_prep(const float* __restrict__ x,
                       const float* __restrict__ W1,
                       const float* __restrict__ W2,
                       float* __restrict__ w1t, float* __restrict__ w2t){
  const int b = blockIdx.x;
  const int t = threadIdx.x;
  const float* src; float* dst;
  size_t off8;
  if (b < 8192){
    off8 = ((size_t)b * 256 + t);                 // 8-block index
    src = W1 + off8 * 8;  dst = w1t + off8 * 8;
  } else if (b < 16384){
    off8 = ((size_t)(b - 8192) * 256 + t);
    src = W2 + off8 * 8;  dst = w2t + off8 * 8;
  } else {
    size_t i8 = ((size_t)(b - 16384) * 256 + t);  // over NSLOT*1024/8
    int nk  = (int)(i8 >> 7);                     // 128 8-blocks per row
    int kb  = (int)(i8 & 127);
    int slot = g_tok_slot[nk];
    src = x    + ((size_t)(nk >> 1)) * HDIM + kb * 8;
    dst = g_xg + ((size_t)slot)      * HDIM + kb * 8;
  }
  float4 lo = *(const float4*)(src);
  float4 hi = *(const float4*)(src + 4);
  float4 o0, o1;
  o0.x = rnaf(lo.x); o0.y = rnaf(hi.x); o0.z = rnaf(lo.y); o0.w = rnaf(hi.y);
  o1.x = rnaf(lo.z); o1.y = rnaf(hi.z); o1.z = rnaf(lo.w); o1.w = rnaf(hi.w);
  *(float4*)(dst)     = o0;
  *(float4*)(dst + 4) = o1;
}

// ---------------- grouped GEMM (tf32 mma.sync, LDS.64 fragments) --------------
// MODE 0 (fc1): g_hid[slot,i] = rna(silu( sum_h xg[slot,h]*W1t[e,i,h] )), K=1024
// MODE 1 (fc2): g_out2[slot,h] =            sum_i hid[slot,i]*W2t[e,h,i], K=2048
// BM=BN=128, BK=32 (128B rows, chunk-XOR swizzle), 256 threads (8 warps 4x2,
// warp 32x64), 3-stage cp.async pipeline (2 ktiles in flight).
template<int MODE>
__global__ __launch_bounds__(256, 2) void k_gemm(){
  constexpr int KD   = (MODE == 0) ? HDIM : IDIM;
  constexpr int KT   = KD / BK;
  constexpr int ODIM = (MODE == 0) ? IDIM : HDIM;

  const int e  = blockIdx.z;
  const int Me = g_counts[e];
  const int m0 = blockIdx.y * BM;
  if (m0 >= Me) return;
  const int rowbase = g_offsets[e] + m0;
  const int n0 = blockIdx.x * BN;

  const float* Abase = ((MODE == 0) ? g_xg : g_hid) + (size_t)rowbase * KD;
  const float* Bbase = ((MODE == 0) ? g_W1t : g_W2t)
                     + (size_t)e * (size_t)HDIM * IDIM + (size_t)n0 * KD;
  float* Outb = (MODE == 0) ? g_hid : g_out2;

  extern __shared__ float sm[];
  float* smA = sm;
  float* smB = sm + STAGES * STAGE_F;

  const int tid = threadIdx.x;

  // cp.async mapping: tile = 128 rows x 8 chunks(16B); 1024 chunks per operand;
  // 256 threads x 4 chunks each. Swizzle: phys_chunk = c ^ (row & 7).
  const float* ag[4]; const float* bg[4];
  uint32_t asw[4], bsw[4];
  #pragma unroll
  for (int j = 0; j < 4; ++j){
    int q   = tid + 256 * j;        // 0..1023
    int row = q >> 3;               // 0..127
    int c   = q & 7;
    int pc  = c ^ (row & 7);
    ag[j] = Abase + (size_t)row * KD + c * 4;
    bg[j] = Bbase + (size_t)row * KD + c * 4;
    asw[j] = (uint32_t)__cvta_generic_to_shared(smA + row * BK + pc * 4);
    bsw[j] = (uint32_t)__cvta_generic_to_shared(smB + row * BK + pc * 4);
  }

  auto issue = [&](int kt){
    const uint32_t so = (uint32_t)((kt % STAGES) * STAGE_F * 4);
    const int ko = kt * BK;
    #pragma unroll
    for (int j = 0; j < 4; ++j){
      cpasync16(asw[j] + so, ag[j] + ko);
      cpasync16(bsw[j] + so, bg[j] + ko);
    }
    asm volatile("cp.async.commit_group;" ::: "memory");
  };

  issue(0); issue(1);

  const int lane = tid & 31, warp = tid >> 5;
  const int wm = warp >> 1, wn = warp & 1;       // 4x2 warps, 32x64 warp tile
  const int g = lane >> 2, tig = lane & 3;

  float c[2][8][4];
  #pragma unroll
  for (int mi = 0; mi < 2; ++mi)
    #pragma unroll
    for (int ni = 0; ni < 8; ++ni)
      #pragma unroll
      for (int j = 0; j < 4; ++j) c[mi][ni][j] = 0.f;

  for (int kt = 0; kt < KT; ++kt){
    asm volatile("cp.async.wait_group 1;" ::: "memory");  // stage kt landed
    __syncthreads();                // all warps finished frags of kt-1
    if (kt + 2 < KT) issue(kt + 2);

    const float* As = smA + (kt % STAGES) * STAGE_F;
    const float* Bs = smB + (kt % STAGES) * STAGE_F;

    #pragma unroll
    for (int ks = 0; ks < 4; ++ks){           // 4 logical k8-blocks per ktile
      // fragment float2: chunk = (2ks + tig/2) ^ g, sub = tig&1 (uniform all rows)
      const int fo = (((ks << 1) | (tig >> 1)) ^ g) * 4 + ((tig & 1) << 1);
      float2 a0[2], a1[2];
      #pragma unroll
      for (int mi = 0; mi < 2; ++mi){
        const int r = wm*32 + mi*16 + g;
        a0[mi] = *(const float2*)(As + r*BK + fo);
        a1[mi] = *(const float2*)(As + (r + 8)*BK + fo);
      }
      float2 bv[8];
      #pragma unroll
      for (int ni = 0; ni < 8; ++ni){
        const int bn = wn*64 + ni*8 + g;
        bv[ni] = *(const float2*)(Bs + bn*BK + fo);
      }
      #pragma unroll
      for (int mi = 0; mi < 2; ++mi){
        uint32_t a[4] = { __float_as_uint(a0[mi].x), __float_as_uint(a1[mi].x),
                          __float_as_uint(a0[mi].y), __float_as_uint(a1[mi].y) };
        #pragma unroll
        for (int ni = 0; ni < 8; ++ni){
          uint32_t b[2] = { __float_as_uint(bv[ni].x), __float_as_uint(bv[ni].y) };
          mma_tf32(c[mi][ni], a, b);
        }
      }
    }
  }

  // epilogue (pad rows are writable scratch; no masks)
  #pragma unroll
  for (int mi = 0; mi < 2; ++mi){
    const int r0 = wm*32 + mi*16 + g;
    float* o0 = Outb + (size_t)(rowbase + r0    ) * ODIM + n0;
    float* o1 = Outb + (size_t)(rowbase + r0 + 8) * ODIM + n0;
    if (MODE == 0){
      // hid must be written in PERMUTED k-layout (it is fc2's A).
      // logical cols (2*tig, 2*tig+1) -> phys (p, p+2), p = 4*(tig&1) + (tig>>1)
      const int p = ((tig & 1) << 2) + (tig >> 1);
      #pragma unroll
      for (int ni = 0; ni < 8; ++ni){
        const int base = wn*64 + ni*8;
        o0[base + p]     = rnaf(silu_f(c[mi][ni][0]));
        o0[base + p + 2] = rnaf(silu_f(c[mi][ni][1]));
        o1[base + p]     = rnaf(silu_f(c[mi][ni][2]));
        o1[base + p + 2] = rnaf(silu_f(c[mi][ni][3]));
      }
    } else {
      #pragma unroll
      for (int ni = 0; ni < 8; ++ni){
        const int col = wn*64 + ni*8 + 2*tig;
        *(float2*)(o0 + col) = make_float2(c[mi][ni][0], c[mi][ni][1]);
        *(float2*)(o1 + col) = make_float2(c[mi][ni][2], c[mi][ni][3]);
      }
    }
  }
}

// ---------------- combine: out[n] = w0*out2[s0] + w1*out2[s1] -----------------
__global__ void k_combine(float* __restrict__ out){
  const int idx = blockIdx.x * blockDim.x + threadIdx.x;
  const int n = idx >> 8;
  const int c = (idx & 255) * 4;
  const int s0 = g_tok_slot[2*n], s1 = g_tok_slot[2*n+1];
  const float w0 = g_topk_val[2*n], w1 = g_topk_val[2*n+1];
  const float4 v0 = *(const float4*)(g_out2 + (size_t)s0 * HDIM + c);
  const float4 v1 = *(const float4*)(g_out2 + (size_t)s1 * HDIM + c);
  float4 r;
  r.x = fmaf(w0, v0.x, w1 * v1.x);
  r.y = fmaf(w0, v0.y, w1 * v1.y);
  r.z = fmaf(w0, v0.z, w1 * v1.z);
  r.w = fmaf(w0, v0.w, w1 * v1.w);
  *(float4*)(out + (size_t)n * HDIM + c) = r;
}

// ---------------- launch ------------------------------------------------------
// Harness emits ~2 profileable launches before ours and ncu uses -s 5 -c 1, so
// OUR launch #3 gets profiled -> make it k_gemm<0>.
extern "C" void kernel_launch(void* const* d_in, const int* in_sizes, int n_in,
                              void* d_out, int out_size){
  const float* x  = (const float*)d_in[0];   // [4,2048,1024]
  const float* Wg = (const float*)d_in[1];   // [8,1024]
  const float* W1 = (const float*)d_in[2];   // [8,2048,1024]
  const float* W2 = (const float*)d_in[3];   // [8,1024,2048]
  float* out = (float*)d_out;                // [4,2048,1024]
  (void)in_sizes; (void)n_in; (void)out_size;

  const int smem_bytes = SMEM_FLOATS * (int)sizeof(float);   // 98304
  cudaFuncSetAttribute(k_gemm<0>, cudaFuncAttributeMaxDynamicSharedMemorySize, smem_bytes);
  cudaFuncSetAttribute(k_gemm<1>, cudaFuncAttributeMaxDynamicSharedMemorySize, smem_bytes);

  float* w1t; float* w2t; int* cnts;
  cudaGetSymbolAddress((void**)&w1t, g_W1t);
  cudaGetSymbolAddress((void**)&w2t, g_W2t);
  cudaGetSymbolAddress((void**)&cnts, g_counts);

  cudaMemsetAsync(cnts, 0, NEXP * sizeof(int));
  k_gate   <<<NTOK/8, 256>>>(x, Wg);            // #0
  k_routes <<<1, 256>>>();                      // #1
  k_prep   <<<24576, 256>>>(x, W1, W2, w1t, w2t); // #2
  k_gemm<0><<<dim3(IDIM/BN, NSLOT/BM, NEXP), 256, smem_bytes>>>();  // #3 <- profiled
  k_gemm<1><<<dim3(HDIM/BN, NSLOT/BM, NEXP), 256, smem_bytes>>>();  // #4
  k_combine<<<NTOK, 256>>>(out);                // #5
}

// round 15
// speedup vs baseline: 1.7448x; 1.0242x over previous
#include <cuda_runtime.h>
#include <cstdint>
#include <math.h>

// Problem constants (fixed shapes)
#define NTOK 8192          // B*T
#define HDIM 1024
#define IDIM 2048
#define NEXP 8
#define NSLOT (NTOK*2)     // top_k = 2
#define NPAD  (NSLOT + 1152)  // padded slot capacity (expert regions 128-aligned)

// GEMM tiling: CTA 128x256, warp 64x64 (8 warps 2x4), BK=32, 4-stage cp.async
#define BM 128
#define BN 256
#define BK 32
#define STAGES 4
#define STAGE_AF (BM * BK)         // 4096 floats (16 KB) per A stage
#define STAGE_BF (BN * BK)         // 8192 floats (32 KB) per B stage
#define SMEM_FLOATS (STAGES * (STAGE_AF + STAGE_BF))   // 49152 floats = 196608 B

// ---------------- scratch (device globals: no allocations allowed) ----------
// g_xg / g_hid / W1t / W2t use a PERMUTED k-layout: within each 8-block,
// element order is [k0, k0+4, k0+1, k0+5, k0+2, k0+6, k0+3, k0+7], so an mma
// fragment pair (tig, tig+4) is one contiguous float2.
__device__ int   g_counts[NEXP];
__device__ int   g_offsets[NEXP+1];          // 128-aligned expert region starts
__device__ int   g_topk_idx[NTOK*2];
__device__ float g_topk_val[NTOK*2];
__device__ int   g_tok_slot[NTOK*2];         // (token,k) -> padded slot
__device__ float g_xg  [(size_t)NPAD * HDIM];   // gathered x (tf32, permuted k)
__device__ float g_hid [(size_t)NPAD * IDIM];   // fc1 acts   (tf32, permuted k)
__device__ float g_out2[(size_t)NPAD * HDIM];   // fc2 per-slot outputs (linear)
__device__ float g_W1t[(size_t)NEXP * IDIM * HDIM];  // W1 (tf32, permuted k)
__device__ float g_W2t[(size_t)NEXP * HDIM * IDIM];  // W2 (tf32, permuted k)

// ---------------- helpers ----------------------------------------------------
__device__ __forceinline__ float rnaf(float x){
  uint32_t u; asm("cvt.rna.tf32.f32 %0, %1;" : "=r"(u) : "f"(x));
  return __uint_as_float(u);
}
__device__ __forceinline__ float silu_f(float v){
  return v * (1.0f / (1.0f + __expf(-v)));
}
__device__ __forceinline__ void cpasync16(uint32_t saddr, const void* g){
  asm volatile("cp.async.cg.shared.global [%0], [%1], 16;" :: "r"(saddr), "l"(g));
}
__device__ __forceinline__ void mma_tf32(float* c, const uint32_t* a, const uint32_t* b){
  asm volatile(
    "mma.sync.aligned.m16n8k8.row.col.f32.tf32.tf32.f32 "
    "{%0,%1,%2,%3}, {%4,%5,%6,%7}, {%8,%9}, {%0,%1,%2,%3};\n"
    : "+f"(c[0]), "+f"(c[1]), "+f"(c[2]), "+f"(c[3])
    : "r"(a[0]), "r"(a[1]), "r"(a[2]), "r"(a[3]),
      "r"(b[0]), "r"(b[1]));
}

// ---------------- routing -----------------------------------------------------
// One warp per token: logits (fp32 exact), softmax, top-2.
__global__ void k_gate(const float* __restrict__ x, const float* __restrict__ Wg){
  int gid  = blockIdx.x * blockDim.x + threadIdx.x;
  int n    = gid >> 5;
  int lane = gid & 31;
  if (n >= NTOK) return;
  const float* xr = x + (size_t)n * HDIM;
  float acc[NEXP];
  #pragma unroll
  for (int e = 0; e < NEXP; ++e) acc[e] = 0.f;
  for (int h = lane; h < HDIM; h += 32){
    float xv = xr[h];
    #pragma unroll
    for (int e = 0; e < NEXP; ++e) acc[e] = fmaf(xv, Wg[e*HDIM + h], acc[e]);
  }
  #pragma unroll
  for (int e = 0; e < NEXP; ++e){
    #pragma unroll
    for (int o = 16; o > 0; o >>= 1) acc[e] += __shfl_xor_sync(0xffffffffu, acc[e], o);
  }
  float mx = acc[0];
  #pragma unroll
  for (int e = 1; e < NEXP; ++e) mx = fmaxf(mx, acc[e]);
  float p[NEXP], s = 0.f;
  #pragma unroll
  for (int e = 0; e < NEXP; ++e){ p[e] = __expf(acc[e] - mx); s += p[e]; }
  float inv = 1.f / s;
  // top-2, strict > keeps lowest index on ties (matches jax.lax.top_k)
  int i0 = 0; float v0 = p[0];
  #pragma unroll
  for (int e = 1; e < NEXP; ++e) if (p[e] > v0){ v0 = p[e]; i0 = e; }
  int i1 = -1; float v1 = -1.f;
  #pragma unroll
  for (int e = 0; e < NEXP; ++e) if (e != i0 && p[e] > v1){ v1 = p[e]; i1 = e; }
  if (lane == 0){
    g_topk_idx[2*n]   = i0; g_topk_val[2*n]   = v0 * inv;
    g_topk_idx[2*n+1] = i1; g_topk_val[2*n+1] = v1 * inv;
    atomicAdd(&g_counts[i0], 1);
    atomicAdd(&g_counts[i1], 1);
  }
}

// Fused: 128-aligned offsets + slot assignment. Single block.
__global__ void k_routes(){
  __shared__ int sc[NEXP];
  const int tid = threadIdx.x;
  if (tid == 0){
    int s = 0;
    for (int e = 0; e < NEXP; ++e){
      g_offsets[e] = s;
      s += (g_counts[e] + 127) & ~127;     // pad region to 128 rows
    }
    g_offsets[NEXP] = s;
  }
  __syncthreads();
  if (tid < NEXP) sc[tid] = g_offsets[tid];
  __syncthreads();
  for (int n = tid; n < NTOK; n += blockDim.x){
    #pragma unroll
    for (int k = 0; k < 2; ++k){
      int e = g_topk_idx[2*n + k];
      int pos = atomicAdd(&sc[e], 1);
      g_tok_slot[2*n + k] = pos;
    }
  }
}

// Fused prep: tf32-round + k-permute W1, W2, and the gathered x rows.
//   blocks [0, 8192)      : W1,  blocks [8192, 16384): W2,
//   blocks [16384, 24576) : gather x into slot order
__global__ void k_prep(const float* __restrict__ x,
                       const float* __restrict__ W1,
                       const float* __restrict__ W2,
                       float* __restrict__ w1t, float* __restrict__ w2t){
  const int b = blockIdx.x;
  const int t = threadIdx.x;
  const float* src; float* dst;
  size_t off8;
  if (b < 8192){
    off8 = ((size_t)b * 256 + t);
    src = W1 + off8 * 8;  dst = w1t + off8 * 8;
  } else if (b < 16384){
    off8 = ((size_t)(b - 8192) * 256 + t);
    src = W2 + off8 * 8;  dst = w2t + off8 * 8;
  } else {
    size_t i8 = ((size_t)(b - 16384) * 256 + t);
    int nk  = (int)(i8 >> 7);                     // 128 8-blocks per row
    int kb  = (int)(i8 & 127);
    int slot = g_tok_slot[nk];
    src = x    + ((size_t)(nk >> 1)) * HDIM + kb * 8;
    dst = g_xg + ((size_t)slot)      * HDIM + kb * 8;
  }
  float4 lo = *(const float4*)(src);
  float4 hi = *(const float4*)(src + 4);
  float4 o0, o1;
  o0.x = rnaf(lo.x); o0.y = rnaf(hi.x); o0.z = rnaf(lo.y); o0.w = rnaf(hi.y);
  o1.x = rnaf(lo.z); o1.y = rnaf(hi.z); o1.z = rnaf(lo.w); o1.w = rnaf(hi.w);
  *(float4*)(dst)     = o0;
  *(float4*)(dst + 4) = o1;
}

// ---------------- grouped GEMM (tf32 mma.sync, 64x64 warp tiles) --------------
// MODE 0 (fc1): g_hid[slot,i] = rna(silu( sum_h xg[slot,h]*W1t[e,i,h] )), K=1024
// MODE 1 (fc2): g_out2[slot,h] =            sum_i hid[slot,i]*W2t[e,h,i], K=2048
// CTA tile 128x256, 8 warps (2x4), warp 64x64, BK=32 (128B rows, chunk-XOR
// swizzle), 4-stage cp.async pipeline with strict group accounting.
template<int MODE>
__global__ __launch_bounds__(256) void k_gemm(){
  constexpr int KD   = (MODE == 0) ? HDIM : IDIM;
  constexpr int KT   = KD / BK;
  constexpr int ODIM = (MODE == 0) ? IDIM : HDIM;

  const int e  = blockIdx.z;
  const int Me = g_counts[e];
  const int m0 = blockIdx.y * BM;
  if (m0 >= Me) return;
  const int rowbase = g_offsets[e] + m0;
  const int n0 = blockIdx.x * BN;

  const float* Abase = ((MODE == 0) ? g_xg : g_hid) + (size_t)rowbase * KD;
  const float* Bbase = ((MODE == 0) ? g_W1t : g_W2t)
                     + (size_t)e * (size_t)HDIM * IDIM + (size_t)n0 * KD;
  float* Outb = (MODE == 0) ? g_hid : g_out2;

  extern __shared__ float sm[];
  float* smA = sm;                       // STAGES * STAGE_AF
  float* smB = sm + STAGES * STAGE_AF;   // STAGES * STAGE_BF

  const int tid = threadIdx.x;

  // cp.async mapping: chunk = 16B. tid -> (rbase = tid>>3, c = tid&7).
  // A: rows rbase+32j, j=0..3.  B: rows rbase+32j, j=0..7.
  // Swizzle phys chunk pc = c ^ (rbase&7)  (j-invariant: rows step by 32).
  const int rb = tid >> 3, cc = tid & 7;
  const int pc = cc ^ (rb & 7);
  const float* ag0 = Abase + (size_t)rb * KD + cc * 4;
  const float* bg0 = Bbase + (size_t)rb * KD + cc * 4;
  const uint32_t asw0 = (uint32_t)__cvta_generic_to_shared(smA + rb * BK + pc * 4);
  const uint32_t bsw0 = (uint32_t)__cvta_generic_to_shared(smB + rb * BK + pc * 4);

  auto issue = [&](int kt){
    const uint32_t soA = (uint32_t)((kt & (STAGES-1)) * STAGE_AF * 4);
    const uint32_t soB = (uint32_t)((kt & (STAGES-1)) * STAGE_BF * 4);
    const int ko = kt * BK;
    #pragma unroll
    for (int j = 0; j < 4; ++j)
      cpasync16(asw0 + soA + j * (32*BK*4), ag0 + ko + (size_t)j * 32 * KD);
    #pragma unroll
    for (int j = 0; j < 8; ++j)
      cpasync16(bsw0 + soB + j * (32*BK*4), bg0 + ko + (size_t)j * 32 * KD);
  };

  issue(0); asm volatile("cp.async.commit_group;" ::: "memory");
  issue(1); asm volatile("cp.async.commit_group;" ::: "memory");
  issue(2); asm volatile("cp.async.commit_group;" ::: "memory");

  const int lane = tid & 31, warp = tid >> 5;
  const int wm = warp >> 2, wn = warp & 3;       // 2x4 warps, 64x64 warp tile
  const int g = lane >> 2, tig = lane & 3;

  float c[4][8][4];
  #pragma unroll
  for (int mi = 0; mi < 4; ++mi)
    #pragma unroll
    for (int ni = 0; ni < 8; ++ni)
      #pragma unroll
      for (int j = 0; j < 4; ++j) c[mi][ni][j] = 0.f;

  for (int kt = 0; kt < KT; ++kt){
    // exactly 3 groups are pending here (tail groups may be empty commits):
    asm volatile("cp.async.wait_group 2;" ::: "memory");  // stage kt landed
    __syncthreads();                 // all warps consumed stage kt-1's frags
    if (kt + 3 < KT) issue(kt + 3);
    asm volatile("cp.async.commit_group;" ::: "memory");  // count even if empty

    const float* As = smA + (kt & (STAGES-1)) * STAGE_AF;
    const float* Bs = smB + (kt & (STAGES-1)) * STAGE_BF;

    #pragma unroll
    for (int ks = 0; ks < 4; ++ks){           // 4 logical k8-blocks per ktile
      // fragment float2: chunk = (2ks + tig/2) ^ g, sub-pair = tig&1
      const int fo = (((ks << 1) | (tig >> 1)) ^ g) * 4 + ((tig & 1) << 1);
      float2 a0[4], a1[4];
      #pragma unroll
      for (int mi = 0; mi < 4; ++mi){
        const int r = wm*64 + mi*16 + g;
        a0[mi] = *(const float2*)(As + r*BK + fo);
        a1[mi] = *(const float2*)(As + (r + 8)*BK + fo);
      }
      float2 bv[8];
      #pragma unroll
      for (int ni = 0; ni < 8; ++ni){
        const int bn = wn*64 + ni*8 + g;
        bv[ni] = *(const float2*)(Bs + bn*BK + fo);
      }
      #pragma unroll
      for (int mi = 0; mi < 4; ++mi){
        uint32_t a[4] = { __float_as_uint(a0[mi].x), __float_as_uint(a1[mi].x),
                          __float_as_uint(a0[mi].y), __float_as_uint(a1[mi].y) };
        #pragma unroll
        for (int ni = 0; ni < 8; ++ni){
          uint32_t b[2] = { __float_as_uint(bv[ni].x), __float_as_uint(bv[ni].y) };
          mma_tf32(c[mi][ni], a, b);
        }
      }
    }
  }

  // epilogue (pad rows are writable scratch; no masks)
  #pragma unroll
  for (int mi = 0; mi < 4; ++mi){
    const int r0 = wm*64 + mi*16 + g;
    float* o0 = Outb + (size_t)(rowbase + r0    ) * ODIM + n0;
    float* o1 = Outb + (size_t)(rowbase + r0 + 8) * ODIM + n0;
    if (MODE == 0){
      // hid is fc2's A: write in PERMUTED k-layout.
      // logical cols (2*tig, 2*tig+1) -> phys (p, p+2), p = 4*(tig&1) + (tig>>1)
      const int p = ((tig & 1) << 2) + (tig >> 1);
      #pragma unroll
      for (int ni = 0; ni < 8; ++ni){
        const int base = wn*64 + ni*8;
        o0[base + p]     = rnaf(silu_f(c[mi][ni][0]));
        o0[base + p + 2] = rnaf(silu_f(c[mi][ni][1]));
        o1[base + p]     = rnaf(silu_f(c[mi][ni][2]));
        o1[base + p + 2] = rnaf(silu_f(c[mi][ni][3]));
      }
    } else {
      #pragma unroll
      for (int ni = 0; ni < 8; ++ni){
        const int col = wn*64 + ni*8 + 2*tig;
        *(float2*)(o0 + col) = make_float2(c[mi][ni][0], c[mi][ni][1]);
        *(float2*)(o1 + col) = make_float2(c[mi][ni][2], c[mi][ni][3]);
      }
    }
  }
}

// ---------------- combine: out[n] = w0*out2[s0] + w1*out2[s1] -----------------
__global__ void k_combine(float* __restrict__ out){
  const int idx = blockIdx.x * blockDim.x + threadIdx.x;
  const int n = idx >> 8;
  const int c = (idx & 255) * 4;
  const int s0 = g_tok_slot[2*n], s1 = g_tok_slot[2*n+1];
  const float w0 = g_topk_val[2*n], w1 = g_topk_val[2*n+1];
  const float4 v0 = *(const float4*)(g_out2 + (size_t)s0 * HDIM + c);
  const float4 v1 = *(const float4*)(g_out2 + (size_t)s1 * HDIM + c);
  float4 r;
  r.x = fmaf(w0, v0.x, w1 * v1.x);
  r.y = fmaf(w0, v0.y, w1 * v1.y);
  r.z = fmaf(w0, v0.z, w1 * v1.z);
  r.w = fmaf(w0, v0.w, w1 * v1.w);
  *(float4*)(out + (size_t)n * HDIM + c) = r;
}

// ---------------- launch ------------------------------------------------------
// Launch order keeps k_gemm<0> as OUR launch #3 (profiled by ncu -s 5 -c 1).
extern "C" void kernel_launch(void* const* d_in, const int* in_sizes, int n_in,
                              void* d_out, int out_size){
  const float* x  = (const float*)d_in[0];   // [4,2048,1024]
  const float* Wg = (const float*)d_in[1];   // [8,1024]
  const float* W1 = (const float*)d_in[2];   // [8,2048,1024]
  const float* W2 = (const float*)d_in[3];   // [8,1024,2048]
  float* out = (float*)d_out;                // [4,2048,1024]
  (void)in_sizes; (void)n_in; (void)out_size;

  const int smem_bytes = SMEM_FLOATS * (int)sizeof(float);   // 196608
  cudaFuncSetAttribute(k_gemm<0>, cudaFuncAttributeMaxDynamicSharedMemorySize, smem_bytes);
  cudaFuncSetAttribute(k_gemm<1>, cudaFuncAttributeMaxDynamicSharedMemorySize, smem_bytes);

  float* w1t; float* w2t; int* cnts;
  cudaGetSymbolAddress((void**)&w1t, g_W1t);
  cudaGetSymbolAddress((void**)&w2t, g_W2t);
  cudaGetSymbolAddress((void**)&cnts, g_counts);

  cudaMemsetAsync(cnts, 0, NEXP * sizeof(int));
  k_gate   <<<NTOK/8, 256>>>(x, Wg);              // #0
  k_routes <<<1, 256>>>();                        // #1
  k_prep   <<<24576, 256>>>(x, W1, W2, w1t, w2t); // #2
  k_gemm<0><<<dim3(IDIM/BN, NSLOT/BM, NEXP), 256, smem_bytes>>>();  // #3 <- profiled
  k_gemm<1><<<dim3(HDIM/BN, NSLOT/BM, NEXP), 256, smem_bytes>>>();  // #4
  k_combine<<<NTOK, 256>>>(out);                  // #5
}

// round 17
// speedup vs baseline: 1.9376x; 1.1105x over previous
#include <cuda_runtime.h>
#include <cstdint>
#include <math.h>

// Problem constants (fixed shapes)
#define NTOK 8192          // B*T
#define HDIM 1024
#define IDIM 2048
#define NEXP 8
#define NSLOT (NTOK*2)     // top_k = 2
#define NPAD  (NSLOT + 1152)  // padded slot capacity (expert regions 128-aligned)

// GEMM tiling: CTA 128x128, 128 threads (4 warps 2x2, warp 64x64), BK=32,
// 3-stage cp.async -> 96 KB smem, ~178 regs => 2 CTAs/SM (decoupled barriers).
#define BM 128
#define BN 128
#define BK 32
#define STAGES 3
#define STAGE_AF (BM * BK)         // 4096 floats (16 KB) per A stage
#define STAGE_BF (BN * BK)         // 4096 floats (16 KB) per B stage
#define SMEM_FLOATS (STAGES * (STAGE_AF + STAGE_BF))   // 24576 floats = 98304 B

// ---------------- scratch (device globals: no allocations allowed) ----------
// g_xg / g_hid / W1t / W2t use a PERMUTED k-layout: within each 8-block,
// element order is [k0, k0+4, k0+1, k0+5, k0+2, k0+6, k0+3, k0+7], so an mma
// fragment pair (tig, tig+4) is one contiguous float2.
__device__ int   g_counts[NEXP];
__device__ int   g_offsets[NEXP+1];          // 128-aligned expert region starts
__device__ int   g_topk_idx[NTOK*2];
__device__ float g_topk_val[NTOK*2];
__device__ int   g_tok_slot[NTOK*2];         // (token,k) -> padded slot
__device__ float g_xg  [(size_t)NPAD * HDIM];   // gathered x (tf32, permuted k)
__device__ float g_hid [(size_t)NPAD * IDIM];   // fc1 acts   (tf32, permuted k)
__device__ float g_out2[(size_t)NPAD * HDIM];   // fc2 per-slot outputs (linear)
__device__ float g_W1t[(size_t)NEXP * IDIM * HDIM];  // W1 (tf32, permuted k)
__device__ float g_W2t[(size_t)NEXP * HDIM * IDIM];  // W2 (tf32, permuted k)

// ---------------- helpers ----------------------------------------------------
__device__ __forceinline__ float rnaf(float x){
  uint32_t u; asm("cvt.rna.tf32.f32 %0, %1;" : "=r"(u) : "f"(x));
  return __uint_as_float(u);
}
__device__ __forceinline__ float silu_f(float v){
  return v * (1.0f / (1.0f + __expf(-v)));
}
__device__ __forceinline__ void cpasync16(uint32_t saddr, const void* g){
  asm volatile("cp.async.cg.shared.global [%0], [%1], 16;" :: "r"(saddr), "l"(g));
}
__device__ __forceinline__ void mma_tf32(float* c, const uint32_t* a, const uint32_t* b){
  asm volatile(
    "mma.sync.aligned.m16n8k8.row.col.f32.tf32.tf32.f32 "
    "{%0,%1,%2,%3}, {%4,%5,%6,%7}, {%8,%9}, {%0,%1,%2,%3};\n"
    : "+f"(c[0]), "+f"(c[1]), "+f"(c[2]), "+f"(c[3])
    : "r"(a[0]), "r"(a[1]), "r"(a[2]), "r"(a[3]),
      "r"(b[0]), "r"(b[1]));
}

// ---------------- routing -----------------------------------------------------
// One warp per token: logits (fp32 exact), softmax, top-2.
__global__ void k_gate(const float* __restrict__ x, const float* __restrict__ Wg){
  int gid  = blockIdx.x * blockDim.x + threadIdx.x;
  int n    = gid >> 5;
  int lane = gid & 31;
  if (n >= NTOK) return;
  const float* xr = x + (size_t)n * HDIM;
  float acc[NEXP];
  #pragma unroll
  for (int e = 0; e < NEXP; ++e) acc[e] = 0.f;
  for (int h = lane; h < HDIM; h += 32){
    float xv = xr[h];
    #pragma unroll
    for (int e = 0; e < NEXP; ++e) acc[e] = fmaf(xv, Wg[e*HDIM + h], acc[e]);
  }
  #pragma unroll
  for (int e = 0; e < NEXP; ++e){
    #pragma unroll
    for (int o = 16; o > 0; o >>= 1) acc[e] += __shfl_xor_sync(0xffffffffu, acc[e], o);
  }
  float mx = acc[0];
  #pragma unroll
  for (int e = 1; e < NEXP; ++e) mx = fmaxf(mx, acc[e]);
  float p[NEXP], s = 0.f;
  #pragma unroll
  for (int e = 0; e < NEXP; ++e){ p[e] = __expf(acc[e] - mx); s += p[e]; }
  float inv = 1.f / s;
  // top-2, strict > keeps lowest index on ties (matches jax.lax.top_k)
  int i0 = 0; float v0 = p[0];
  #pragma unroll
  for (int e = 1; e < NEXP; ++e) if (p[e] > v0){ v0 = p[e]; i0 = e; }
  int i1 = -1; float v1 = -1.f;
  #pragma unroll
  for (int e = 0; e < NEXP; ++e) if (e != i0 && p[e] > v1){ v1 = p[e]; i1 = e; }
  if (lane == 0){
    g_topk_idx[2*n]   = i0; g_topk_val[2*n]   = v0 * inv;
    g_topk_idx[2*n+1] = i1; g_topk_val[2*n+1] = v1 * inv;
    atomicAdd(&g_counts[i0], 1);
    atomicAdd(&g_counts[i1], 1);
  }
}

// Fused: 128-aligned offsets + slot assignment. Single block.
__global__ void k_routes(){
  __shared__ int sc[NEXP];
  const int tid = threadIdx.x;
  if (tid == 0){
    int s = 0;
    for (int e = 0; e < NEXP; ++e){
      g_offsets[e] = s;
      s += (g_counts[e] + 127) & ~127;     // pad region to 128 rows
    }
    g_offsets[NEXP] = s;
  }
  __syncthreads();
  if (tid < NEXP) sc[tid] = g_offsets[tid];
  __syncthreads();
  for (int n = tid; n < NTOK; n += blockDim.x){
    #pragma unroll
    for (int k = 0; k < 2; ++k){
      int e = g_topk_idx[2*n + k];
      int pos = atomicAdd(&sc[e], 1);
      g_tok_slot[2*n + k] = pos;
    }
  }
}

// Fused prep: tf32-round + k-permute W1, W2, and the gathered x rows.
//   blocks [0, 8192)      : W1,  blocks [8192, 16384): W2,
//   blocks [16384, 24576) : gather x into slot order
__global__ void k_prep(const float* __restrict__ x,
                       const float* __restrict__ W1,
                       const float* __restrict__ W2,
                       float* __restrict__ w1t, float* __restrict__ w2t){
  const int b = blockIdx.x;
  const int t = threadIdx.x;
  const float* src; float* dst;
  size_t off8;
  if (b < 8192){
    off8 = ((size_t)b * 256 + t);
    src = W1 + off8 * 8;  dst = w1t + off8 * 8;
  } else if (b < 16384){
    off8 = ((size_t)(b - 8192) * 256 + t);
    src = W2 + off8 * 8;  dst = w2t + off8 * 8;
  } else {
    size_t i8 = ((size_t)(b - 16384) * 256 + t);
    int nk  = (int)(i8 >> 7);                     // 128 8-blocks per row
    int kb  = (int)(i8 & 127);
    int slot = g_tok_slot[nk];
    src = x    + ((size_t)(nk >> 1)) * HDIM + kb * 8;
    dst = g_xg + ((size_t)slot)      * HDIM + kb * 8;
  }
  float4 lo = *(const float4*)(src);
  float4 hi = *(const float4*)(src + 4);
  float4 o0, o1;
  o0.x = rnaf(lo.x); o0.y = rnaf(hi.x); o0.z = rnaf(lo.y); o0.w = rnaf(hi.y);
  o1.x = rnaf(lo.z); o1.y = rnaf(hi.z); o1.z = rnaf(lo.w); o1.w = rnaf(hi.w);
  *(float4*)(dst)     = o0;
  *(float4*)(dst + 4) = o1;
}

// ---------------- grouped GEMM (tf32 mma.sync, 64x64 warp tiles) --------------
// MODE 0 (fc1): g_hid[slot,i] = rna(silu( sum_h xg[slot,h]*W1t[e,i,h] )), K=1024
// MODE 1 (fc2): g_out2[slot,h] =            sum_i hid[slot,i]*W2t[e,h,i], K=2048
// CTA 128x128, 128 threads (4 warps 2x2, warp 64x64), BK=32 (128B rows,
// chunk-XOR swizzle), 3-stage cp.async. 2 CTAs/SM -> decoupled barriers.
template<int MODE>
__global__ __launch_bounds__(128, 2) void k_gemm(){
  constexpr int KD   = (MODE == 0) ? HDIM : IDIM;
  constexpr int KT   = KD / BK;
  constexpr int ODIM = (MODE == 0) ? IDIM : HDIM;

  const int e  = blockIdx.z;
  const int Me = g_counts[e];
  const int m0 = blockIdx.y * BM;
  if (m0 >= Me) return;
  const int rowbase = g_offsets[e] + m0;
  const int n0 = blockIdx.x * BN;

  const float* Abase = ((MODE == 0) ? g_xg : g_hid) + (size_t)rowbase * KD;
  const float* Bbase = ((MODE == 0) ? g_W1t : g_W2t)
                     + (size_t)e * (size_t)HDIM * IDIM + (size_t)n0 * KD;
  float* Outb = (MODE == 0) ? g_hid : g_out2;

  extern __shared__ float sm[];
  float* smA = sm;                       // STAGES * STAGE_AF
  float* smB = sm + STAGES * STAGE_AF;   // STAGES * STAGE_BF

  const int tid = threadIdx.x;

  // cp.async mapping: chunk = 16B; tile = 128 rows x 8 chunks = 1024 chunks
  // per operand; 128 threads x 8 chunks each. tid -> (rb = tid>>3, c = tid&7),
  // rows rb+16j (j=0..7). Swizzle pc = c ^ (rb&7) (j-invariant: step 16 rows).
  const int rb = tid >> 3, cc = tid & 7;
  const int pc = cc ^ (rb & 7);
  const float* ag0 = Abase + (size_t)rb * KD + cc * 4;
  const float* bg0 = Bbase + (size_t)rb * KD + cc * 4;
  const uint32_t asw0 = (uint32_t)__cvta_generic_to_shared(smA + rb * BK + pc * 4);
  const uint32_t bsw0 = (uint32_t)__cvta_generic_to_shared(smB + rb * BK + pc * 4);

  auto issue = [&](int kt){
    const uint32_t so = (uint32_t)((kt % STAGES) * STAGE_AF * 4);
    const int ko = kt * BK;
    #pragma unroll
    for (int j = 0; j < 8; ++j)
      cpasync16(asw0 + so + j * (16*BK*4), ag0 + ko + (size_t)j * 16 * KD);
    #pragma unroll
    for (int j = 0; j < 8; ++j)
      cpasync16(bsw0 + so + j * (16*BK*4), bg0 + ko + (size_t)j * 16 * KD);
  };

  issue(0); asm volatile("cp.async.commit_group;" ::: "memory");
  issue(1); asm volatile("cp.async.commit_group;" ::: "memory");

  const int lane = tid & 31, warp = tid >> 5;
  const int wm = warp >> 1, wn = warp & 1;       // 2x2 warps, 64x64 warp tile
  const int g = lane >> 2, tig = lane & 3;

  float c[4][8][4];
  #pragma unroll
  for (int mi = 0; mi < 4; ++mi)
    #pragma unroll
    for (int ni = 0; ni < 8; ++ni)
      #pragma unroll
      for (int j = 0; j < 4; ++j) c[mi][ni][j] = 0.f;

  for (int kt = 0; kt < KT; ++kt){
    // exactly 2 groups pending here (tail groups may be empty commits):
    asm volatile("cp.async.wait_group 1;" ::: "memory");  // stage kt landed
    __syncthreads();                 // all warps consumed stage kt-1's frags
    if (kt + 2 < KT) issue(kt + 2);
    asm volatile("cp.async.commit_group;" ::: "memory");  // count even if empty

    const float* As = smA + (kt % STAGES) * STAGE_AF;
    const float* Bs = smB + (kt % STAGES) * STAGE_BF;

    #pragma unroll
    for (int ks = 0; ks < 4; ++ks){           // 4 logical k8-blocks per ktile
      // fragment float2: chunk = (2ks + tig/2) ^ g, sub-pair = tig&1
      const int fo = (((ks << 1) | (tig >> 1)) ^ g) * 4 + ((tig & 1) << 1);
      float2 a0[4], a1[4];
      #pragma unroll
      for (int mi = 0; mi < 4; ++mi){
        const int r = wm*64 + mi*16 + g;
        a0[mi] = *(const float2*)(As + r*BK + fo);
        a1[mi] = *(const float2*)(As + (r + 8)*BK + fo);
      }
      float2 bv[8];
      #pragma unroll
      for (int ni = 0; ni < 8; ++ni){
        const int bn = wn*64 + ni*8 + g;
        bv[ni] = *(const float2*)(Bs + bn*BK + fo);
      }
      #pragma unroll
      for (int mi = 0; mi < 4; ++mi){
        uint32_t a[4] = { __float_as_uint(a0[mi].x), __float_as_uint(a1[mi].x),
                          __float_as_uint(a0[mi].y), __float_as_uint(a1[mi].y) };
        #pragma unroll
        for (int ni = 0; ni < 8; ++ni){
          uint32_t b[2] = { __float_as_uint(bv[ni].x), __float_as_uint(bv[ni].y) };
          mma_tf32(c[mi][ni], a, b);
        }
      }
    }
  }

  // epilogue (pad rows are writable scratch; no masks)
  #pragma unroll
  for (int mi = 0; mi < 4; ++mi){
    const int r0 = wm*64 + mi*16 + g;
    float* o0 = Outb + (size_t)(rowbase + r0    ) * ODIM + n0;
    float* o1 = Outb + (size_t)(rowbase + r0 + 8) * ODIM + n0;
    if (MODE == 0){
      // hid is fc2's A: write in PERMUTED k-layout.
      // logical cols (2*tig, 2*tig+1) -> phys (p, p+2), p = 4*(tig&1) + (tig>>1)
      const int p = ((tig & 1) << 2) + (tig >> 1);
      #pragma unroll
      for (int ni = 0; ni < 8; ++ni){
        const int base = wn*64 + ni*8;
        o0[base + p]     = rnaf(silu_f(c[mi][ni][0]));
        o0[base + p + 2] = rnaf(silu_f(c[mi][ni][1]));
        o1[base + p]     = rnaf(silu_f(c[mi][ni][2]));
        o1[base + p + 2] = rnaf(silu_f(c[mi][ni][3]));
      }
    } else {
      #pragma unroll
      for (int ni = 0; ni < 8; ++ni){
        const int col = wn*64 + ni*8 + 2*tig;
        *(float2*)(o0 + col) = make_float2(c[mi][ni][0], c[mi][ni][1]);
        *(float2*)(o1 + col) = make_float2(c[mi][ni][2], c[mi][ni][3]);
      }
    }
  }
}

// ---------------- combine: out[n] = w0*out2[s0] + w1*out2[s1] -----------------
__global__ void k_combine(float* __restrict__ out){
  const int idx = blockIdx.x * blockDim.x + threadIdx.x;
  const int n = idx >> 8;
  const int c = (idx & 255) * 4;
  const int s0 = g_tok_slot[2*n], s1 = g_tok_slot[2*n+1];
  const float w0 = g_topk_val[2*n], w1 = g_topk_val[2*n+1];
  const float4 v0 = *(const float4*)(g_out2 + (size_t)s0 * HDIM + c);
  const float4 v1 = *(const float4*)(g_out2 + (size_t)s1 * HDIM + c);
  float4 r;
  r.x = fmaf(w0, v0.x, w1 * v1.x);
  r.y = fmaf(w0, v0.y, w1 * v1.y);
  r.z = fmaf(w0, v0.z, w1 * v1.z);
  r.w = fmaf(w0, v0.w, w1 * v1.w);
  *(float4*)(out + (size_t)n * HDIM + c) = r;
}

// ---------------- launch ------------------------------------------------------
// Launch order keeps k_gemm<0> as OUR launch #3 (profiled by ncu -s 5 -c 1).
extern "C" void kernel_launch(void* const* d_in, const int* in_sizes, int n_in,
                              void* d_out, int out_size){
  const float* x  = (const float*)d_in[0];   // [4,2048,1024]
  const float* Wg = (const float*)d_in[1];   // [8,1024]
  const float* W1 = (const float*)d_in[2];   // [8,2048,1024]
  const float* W2 = (const float*)d_in[3];   // [8,1024,2048]
  float* out = (float*)d_out;                // [4,2048,1024]
  (void)in_sizes; (void)n_in; (void)out_size;

  const int smem_bytes = SMEM_FLOATS * (int)sizeof(float);   // 98304
  cudaFuncSetAttribute(k_gemm<0>, cudaFuncAttributeMaxDynamicSharedMemorySize, smem_bytes);
  cudaFuncSetAttribute(k_gemm<1>, cudaFuncAttributeMaxDynamicSharedMemorySize, smem_bytes);

  float* w1t; float* w2t; int* cnts;
  cudaGetSymbolAddress((void**)&w1t, g_W1t);
  cudaGetSymbolAddress((void**)&w2t, g_W2t);
  cudaGetSymbolAddress((void**)&cnts, g_counts);

  cudaMemsetAsync(cnts, 0, NEXP * sizeof(int));
  k_gate   <<<NTOK/8, 256>>>(x, Wg);              // #0
  k_routes <<<1, 256>>>();                        // #1
  k_prep   <<<24576, 256>>>(x, W1, W2, w1t, w2t); // #2
  k_gemm<0><<<dim3(IDIM/BN, NSLOT/BM, NEXP), 128, smem_bytes>>>();  // #3 <- profiled
  k_gemm<1><<<dim3(HDIM/BN, NSLOT/BM, NEXP), 128, smem_bytes>>>();  // #4
  k_combine<<<NTOK, 256>>>(out);                  // #5
}